// round 13
// baseline (speedup 1.0000x reference)
#include <cuda_runtime.h>
#include <cstdint>
#include <cstddef>

#define H     2048
#define SEQ   4096
#define NCTA  128
#define TPB   512
#define NWARP 16
#define UPC   16            // hidden units per CTA (H / NCTA); 1 unit per warp
#define SROWS 27                          // smem-resident weight rows per CTA
#define SMEM_FLOATS (H + SROWS * H)       // h tile + weight rows
#define SMEM_BYTES  (SMEM_FLOATS * 4)     // 229376 B (max dyn smem 232448)

// Persistent scratch (no allocations allowed anywhere)
__device__ float    g_h[2][H];
__device__ float    g_py[(size_t)SEQ * NCTA];   // t-major: [t][cta]
__device__ unsigned g_count;

__device__ __forceinline__ float sigm_f(float z) {
    return 1.f / (1.f + __expf(-z));
}
__device__ __forceinline__ float tanh_f(float z) {
    z = fminf(20.f, fmaxf(-20.f, z));
    float e = __expf(2.f * z);
    return (e - 1.f) / (e + 1.f);
}

// ---- packed f32x2 helpers (FFMA2 is only reachable via explicit PTX) ----
__device__ __forceinline__ unsigned long long pack2(float lo, float hi) {
    unsigned long long d;
    asm("mov.b64 %0, {%1, %2};" : "=l"(d) : "f"(lo), "f"(hi));
    return d;
}
__device__ __forceinline__ float2 unpack2(unsigned long long v) {
    float lo, hi;
    asm("mov.b64 {%0, %1}, %2;" : "=f"(lo), "=f"(hi) : "l"(v));
    return make_float2(lo, hi);
}
__device__ __forceinline__ unsigned long long fma2(unsigned long long a,
                                                   unsigned long long b,
                                                   unsigned long long c) {
    unsigned long long d;
    asm("fma.rn.f32x2 %0, %1, %2, %3;" : "=l"(d) : "l"(a), "l"(b), "l"(c));
    return d;
}

// Per-replay reset: count=0, h[0]=0. Stream-ordered before the persistent kernel.
__global__ void lstm_init()
{
    int tid = threadIdx.x;
    if (tid == 0) g_count = 0;
    for (int j = tid; j < H; j += blockDim.x) g_h[0][j] = 0.f;
}

__global__ void __launch_bounds__(TPB, 1)
lstm_persistent(const float* __restrict__ inputs,
                const float* __restrict__ w_ih,
                const float* __restrict__ w_hh,
                const float* __restrict__ b_ih,
                const float* __restrict__ b_hh,
                const float* __restrict__ w_out,
                const float* __restrict__ b_out,
                float* __restrict__ out)
{
    extern __shared__ float smem[];
    float* smH = smem;          // H floats
    float* smW = smem + H;      // SROWS * H floats
    __shared__ float s_x;
    __shared__ float s_ypart[NWARP];

    const int tid  = threadIdx.x;
    const int lane = tid & 31;
    const int w    = tid >> 5;            // 0..15, one unit per warp
    const int cta  = blockIdx.x;
    const int u    = cta * UPC + w;       // the unit this warp owns

    // ---- one-time preload of smem-resident weight rows ----
    // rows 0..15 : gate 0 of unit (cta*16 + rl)
    // rows 16..26: gate 1 of unit (cta*16 + rl-16)   [warps 0..10]
    for (int idx = tid; idx < SROWS * H; idx += TPB) {
        int rl  = idx >> 11;          // row-local (H = 2048)
        int col = idx & (H - 1);
        int grow = (rl < 16) ? (0 * H + cta * UPC + rl)
                             : (1 * H + cta * UPC + (rl - 16));
        smW[idx] = w_hh[(size_t)grow * H + col];
    }

    // ---- per-unit constants (lane 0 owns unit u) ----
    float wx0=0,wx1=0,wx2=0,wx3=0, bb0=0,bb1=0,bb2=0,bb3=0, wo=0;
    float c_st = 0.f, h_last = 0.f;
    if (lane == 0) {
        wx0 = w_ih[u];         bb0 = b_ih[u]       + b_hh[u];
        wx1 = w_ih[u +   H];   bb1 = b_ih[u +   H] + b_hh[u +   H];
        wx2 = w_ih[u + 2*H];   bb2 = b_ih[u + 2*H] + b_hh[u + 2*H];
        wx3 = w_ih[u + 3*H];   bb3 = b_ih[u + 3*H] + b_hh[u + 3*H];
        wo  = w_out[u];
    }

    // Row residency per warp (4 rows g0..g3 of unit u):
    //   g0 : smem (all warps)
    //   g1 : smem for warps 0..10, streamed for warps 11..15
    //   g2 : registers (64 regs)
    //   g3 : registers (64 regs)
    const float4* wrow1 = (const float4*)(w_hh + (size_t)(1*H + u) * H);
    const float4* wrow2 = (const float4*)(w_hh + (size_t)(2*H + u) * H);
    const float4* wrow3 = (const float4*)(w_hh + (size_t)(3*H + u) * H);

    // ---- one-time load of register-resident rows g2, g3 (128 regs) ----
    float4 rw2q[16], rw3q[16];
    #pragma unroll
    for (int cc = 0; cc < 16; ++cc) {
        rw2q[cc] = __ldg(&wrow2[cc * 32 + lane]);
        rw3q[cc] = __ldg(&wrow3[cc * 32 + lane]);
    }

    const float4* smH4  = (const float4*)smH;
    const float4* sm_g0 = (const float4*)(smW + w * H);
    // g1 source: smem for warps 0..10, global otherwise (warp-uniform ptr;
    // proven pattern from R4's src5)
    const float4* src1 = (w <= 10) ? (const float4*)(smW + (16 + w) * H)
                                   : wrow1;

    for (int t = 0; t < SEQ; ++t) {
        const int p = t & 1;

        // stage h_{t-1} into smem (bypass L1: written by other SMs).
        // 512 threads x 1 float4 covers H. Step 0 reads lstm_init's zeros.
        {
            const float4* hsrc = (const float4*)g_h[p];
            float4 v = __ldcg(&hsrc[tid]);
            ((float4*)smH)[tid] = v;
        }
        if (tid == 0) s_x = __ldcg(&inputs[t]);
        __syncthreads();

        // ---- 4 row dot-products with packed f32x2 FMA (FFMA2) ----
        // Same per-row accumulation order as prior rounds: chunks ascending,
        // lo pair = (x,y), hi pair = (z,w), final (x+y)+(z+w).
        unsigned long long accL[4], accH[4];
        #pragma unroll
        for (int r = 0; r < 4; ++r) { accL[r] = 0ull; accH[r] = 0ull; }

        #pragma unroll
        for (int cc = 0; cc < 16; ++cc) {
            const int o = cc * 32 + lane;
            float4 hv = smH4[o];
            unsigned long long hL = pack2(hv.x, hv.y);
            unsigned long long hH = pack2(hv.z, hv.w);
            float4 wv[4];
            wv[0] = sm_g0[o];
            wv[1] = src1[o];
            wv[2] = rw2q[cc];
            wv[3] = rw3q[cc];
            #pragma unroll
            for (int r = 0; r < 4; ++r) {
                accL[r] = fma2(pack2(wv[r].x, wv[r].y), hL, accL[r]);
                accH[r] = fma2(pack2(wv[r].z, wv[r].w), hH, accH[r]);
            }
        }

        float rs[4];
        #pragma unroll
        for (int r = 0; r < 4; ++r) {
            float2 lo = unpack2(accL[r]);
            float2 hi = unpack2(accH[r]);
            float s = (lo.x + lo.y) + (hi.x + hi.y);
            #pragma unroll
            for (int o2 = 16; o2; o2 >>= 1)
                s += __shfl_xor_sync(0xffffffffu, s, o2);
            rs[r] = s;
        }

        // ---- gates: lane 0 owns unit u ----
        if (lane == 0) {
            float x  = s_x;
            float zi = rs[0] + x * wx0 + bb0;
            float zf = rs[1] + x * wx1 + bb1;
            float zg = rs[2] + x * wx2 + bb2;
            float zo = rs[3] + x * wx3 + bb3;
            float ig = sigm_f(zi);
            float fg = sigm_f(zf);
            float gg = tanh_f(zg);
            float og = sigm_f(zo);
            c_st = fg * c_st + ig * gg;
            float hn = og * tanh_f(c_st);
            h_last = hn;
            g_h[p ^ 1][u] = hn;
            s_ypart[w] = wo * hn;
        }
        __syncthreads();   // all h stores of this CTA issued

        // ---- publish partial y; count-poll grid barrier (proven R11) ----
        if (tid == 0) {
            float s = 0.f;
            #pragma unroll
            for (int i = 0; i < NWARP; ++i) s += s_ypart[i];
            g_py[(size_t)t * NCTA + cta] = s;   // t-major for fused reduce

            __threadfence();
            atomicAdd(&g_count, 1u);
            const unsigned tgt = (unsigned)(t + 1) * NCTA;
            unsigned v;
            do {
                asm volatile("ld.acquire.gpu.global.u32 %0, [%1];"
                             : "=r"(v) : "l"(&g_count) : "memory");
            } while (v < tgt);
        }
        __syncthreads();
    }

    // final h, c
    if (lane == 0) {
        out[SEQ + u]     = h_last;
        out[SEQ + H + u] = c_st;
    }

    // ---- fused y reduction (proven R9/R11) ----
    if (tid < 32) {
        int t = cta * 32 + tid;
        float bo = __ldcg(&b_out[0]);
        const float4* row = (const float4*)(g_py + (size_t)t * NCTA);
        float s = 0.f;
        #pragma unroll
        for (int q = 0; q < NCTA / 4; ++q) {
            float4 v = __ldcg(&row[q]);
            s += ((v.x + v.y) + (v.z + v.w));   // fixed order, q ascending
        }
        out[t] = s + bo;
    }
}

extern "C" void kernel_launch(void* const* d_in, const int* in_sizes, int n_in,
                              void* d_out, int out_size)
{
    (void)in_sizes; (void)n_in; (void)out_size;
    const float* inputs = (const float*)d_in[0];
    const float* w_ih   = (const float*)d_in[1];
    const float* w_hh   = (const float*)d_in[2];
    const float* b_ih   = (const float*)d_in[3];
    const float* b_hh   = (const float*)d_in[4];
    const float* w_out  = (const float*)d_in[5];
    const float* b_out  = (const float*)d_in[6];
    float* out = (float*)d_out;

    cudaFuncSetAttribute(lstm_persistent,
                         cudaFuncAttributeMaxDynamicSharedMemorySize, SMEM_BYTES);

    lstm_init<<<1, 256>>>();
    lstm_persistent<<<NCTA, TPB, SMEM_BYTES>>>(inputs, w_ih, w_hh, b_ih, b_hh,
                                               w_out, b_out, out);
}

// round 17
// speedup vs baseline: 1.3227x; 1.3227x over previous
#include <cuda_runtime.h>
#include <cstdint>
#include <cstddef>

#define H     2048
#define SEQ   4096
#define NCTA  128
#define TPB   256
#define NWARP 8
#define UPC   16            // hidden units per CTA (H / NCTA)
#define SROWS 27                          // smem-resident weight rows per CTA
#define SMEM_FLOATS (H + SROWS * H)       // h tile + weight rows
#define SMEM_BYTES  (SMEM_FLOATS * 4)     // 229376 B (max dyn smem 232448)

// Persistent scratch (no allocations allowed anywhere)
__device__ float    g_h[2][H];
__device__ float    g_py[(size_t)SEQ * NCTA];   // t-major: [t][cta]
__device__ unsigned g_count;

__device__ __forceinline__ float sigm_f(float z) {
    return 1.f / (1.f + __expf(-z));
}
__device__ __forceinline__ float tanh_f(float z) {
    z = fminf(20.f, fmaxf(-20.f, z));
    float e = __expf(2.f * z);
    return (e - 1.f) / (e + 1.f);
}

// ---- packed f32x2 helpers (FFMA2 is only reachable via explicit PTX) ----
__device__ __forceinline__ unsigned long long pack2(float lo, float hi) {
    unsigned long long d;
    asm("mov.b64 %0, {%1, %2};" : "=l"(d) : "f"(lo), "f"(hi));
    return d;
}
__device__ __forceinline__ float2 unpack2(unsigned long long v) {
    float lo, hi;
    asm("mov.b64 {%0, %1}, %2;" : "=f"(lo), "=f"(hi) : "l"(v));
    return make_float2(lo, hi);
}
__device__ __forceinline__ unsigned long long fma2(unsigned long long a,
                                                   unsigned long long b,
                                                   unsigned long long c) {
    unsigned long long d;
    asm("fma.rn.f32x2 %0, %1, %2, %3;" : "=l"(d) : "l"(a), "l"(b), "l"(c));
    return d;
}

// Per-replay reset: count=0, h[0]=0. Stream-ordered before the persistent kernel.
__global__ void lstm_init()
{
    int tid = threadIdx.x;
    if (tid == 0) g_count = 0;
    for (int j = tid; j < H; j += blockDim.x) g_h[0][j] = 0.f;
}

__global__ void __launch_bounds__(TPB, 1)
lstm_persistent(const float* __restrict__ inputs,
                const float* __restrict__ w_ih,
                const float* __restrict__ w_hh,
                const float* __restrict__ b_ih,
                const float* __restrict__ b_hh,
                const float* __restrict__ w_out,
                const float* __restrict__ b_out,
                float* __restrict__ out)
{
    extern __shared__ float smem[];
    float* smH = smem;          // H floats
    float* smW = smem + H;      // SROWS * H floats
    __shared__ float s_x;
    __shared__ float s_ypart[NWARP];

    const int tid  = threadIdx.x;
    const int lane = tid & 31;
    const int w    = tid >> 5;
    const int cta  = blockIdx.x;
    const int ubase = cta * UPC + 2 * w;   // first unit owned by this warp

    // ---- one-time preload of smem-resident weight rows ----
    // rows 0..23 : warp ww keeps gates k=0..2 of unit (cta*UPC + 2*ww)   [r0..r2]
    // rows 24..26: warps j=0..2 keep gate 1 of unit (cta*UPC + 2*j + 1)  [their r5]
    for (int idx = tid; idx < SROWS * H; idx += TPB) {
        int rl  = idx >> 11;          // row-local (H = 2048)
        int col = idx & (H - 1);
        int grow;
        if (rl < 24) {
            int ww = rl / 3;
            int k  = rl - ww * 3;
            grow = k * H + (cta * UPC + 2 * ww);
        } else {
            int j = rl - 24;
            grow = 1 * H + (cta * UPC + 2 * j + 1);
        }
        smW[idx] = w_hh[(size_t)grow * H + col];
    }

    // ---- per-lane gate constants ----
    // Lanes 0..7: lane = L*4 + gate (L = unit-local 0/1). Each lane owns ONE
    // gate's (w_ih, bias) pair; lanes 0,1 additionally own w_out and c state.
    float wxg = 0.f, bbg = 0.f, wo = 0.f;
    float c_st = 0.f, h_last = 0.f;
    if (lane < 8) {
        int L    = lane >> 2;
        int gate = lane & 3;
        int ug   = ubase + L;
        wxg = w_ih[ug + gate * H];
        bbg = b_ih[ug + gate * H] + b_hh[ug + gate * H];
    }
    if (lane < 2) wo = w_out[ubase + lane];

    // Row map per warp (8 rows r = L*4 + gate, L = unit-local):
    //   r0..r2 : smem   (L0 g0..g2)
    //   r3,r4  : regs   (L0 g3, L1 g0)
    //   r5     : smem for warps 0..2, streamed for warps 3..7 (L1 g1)
    //   r6,r7  : streamed (L1 g2,g3)
    const float4* wrow3 = (const float4*)(w_hh + (size_t)(3*H + ubase + 0) * H);
    const float4* wrow4 = (const float4*)(w_hh + (size_t)(0*H + ubase + 1) * H);
    const float4* wrow5 = (const float4*)(w_hh + (size_t)(1*H + ubase + 1) * H);
    const float4* wrow6 = (const float4*)(w_hh + (size_t)(2*H + ubase + 1) * H);
    const float4* wrow7 = (const float4*)(w_hh + (size_t)(3*H + ubase + 1) * H);

    // ---- one-time load of register-resident rows (128 regs/thread) ----
    float4 rw3q[16], rw4q[16];
    #pragma unroll
    for (int cc = 0; cc < 16; ++cc) {
        rw3q[cc] = __ldg(&wrow3[cc * 32 + lane]);
        rw4q[cc] = __ldg(&wrow4[cc * 32 + lane]);
    }

    const float4* smH4   = (const float4*)smH;
    const float4* smW4_0 = (const float4*)(smW + (w * 3 + 0) * H);
    const float4* smW4_1 = (const float4*)(smW + (w * 3 + 1) * H);
    const float4* smW4_2 = (const float4*)(smW + (w * 3 + 2) * H);
    // r5 source: smem for warps 0..2, global otherwise (warp-uniform pointer)
    const float4* src5 = (w < 3) ? (const float4*)(smW + (24 + w) * H) : wrow5;

    for (int t = 0; t < SEQ; ++t) {
        const int p = t & 1;

        // stage h_{t-1} into smem (must bypass L1: written by other SMs).
        // Step 0 reads zeros published by lstm_init (stream-ordered).
        {
            const float4* hsrc = (const float4*)g_h[p];
            float4 v0 = __ldcg(&hsrc[tid]);
            float4 v1 = __ldcg(&hsrc[tid + TPB]);
            ((float4*)smH)[tid]       = v0;
            ((float4*)smH)[tid + TPB] = v1;
        }
        if (tid == 0) s_x = __ldcg(&inputs[t]);
        __syncthreads();

        // ---- 8 row dot-products with packed f32x2 FMA (FFMA2) ----
        // lo pair = (x,y), hi pair = (z,w): per-component math and the final
        // (x+y)+(z+w) reduction order are identical to the scalar version.
        unsigned long long accL[8], accH[8];
        #pragma unroll
        for (int r = 0; r < 8; ++r) { accL[r] = 0ull; accH[r] = 0ull; }

        #pragma unroll
        for (int cc = 0; cc < 16; ++cc) {
            const int o = cc * 32 + lane;
            float4 hv = smH4[o];
            unsigned long long hL = pack2(hv.x, hv.y);
            unsigned long long hH = pack2(hv.z, hv.w);
            float4 wv[8];
            wv[0] = smW4_0[o];
            wv[1] = smW4_1[o];
            wv[2] = smW4_2[o];
            wv[3] = rw3q[cc];
            wv[4] = rw4q[cc];
            wv[5] = src5[o];
            wv[6] = __ldcg(&wrow6[o]);
            wv[7] = __ldcg(&wrow7[o]);
            #pragma unroll
            for (int r = 0; r < 8; ++r) {
                accL[r] = fma2(pack2(wv[r].x, wv[r].y), hL, accL[r]);
                accH[r] = fma2(pack2(wv[r].z, wv[r].w), hH, accH[r]);
            }
        }

        float rs[8];
        #pragma unroll
        for (int r = 0; r < 8; ++r) {
            float2 lo = unpack2(accL[r]);
            float2 hi = unpack2(accH[r]);
            float s = (lo.x + lo.y) + (hi.x + hi.y);
            #pragma unroll
            for (int o2 = 16; o2; o2 >>= 1)
                s += __shfl_xor_sync(0xffffffffu, s, o2);
            rs[r] = s;   // full result present in ALL lanes
        }

        // ---- gates, parallel across lanes 0..7; ALL collectives convergent ----
        // Lane L*4+g evaluates activation of gate g, unit ubase+L (same ops,
        // same inputs as the serial version -> bit-identical).
        float act = 0.f;
        if (lane < 8) {
            float z = rs[lane] + s_x * wxg + bbg;
            act = ((lane & 3) == 2) ? tanh_f(z) : sigm_f(z);
        }
        // All 32 lanes execute the gathers (srcLane is mod-32; high lanes
        // fetch harmless values). No divergent shuffles.
        {
            int base = (lane & 1) * 4;   // lane0->0..3, lane1->4..7 (others don't care)
            float ig = __shfl_sync(0xffffffffu, act, base + 0);
            float fg = __shfl_sync(0xffffffffu, act, base + 1);
            float gg = __shfl_sync(0xffffffffu, act, base + 2);
            float og = __shfl_sync(0xffffffffu, act, base + 3);
            float py = 0.f;
            if (lane < 2) {
                c_st = fg * c_st + ig * gg;
                float hn = og * tanh_f(c_st);
                h_last = hn;
                g_h[p ^ 1][ubase + lane] = hn;
                py = wo * hn;
            }
            // convergent butterfly in ALL lanes (py=0 outside lanes 0,1)
            py += __shfl_xor_sync(0xffffffffu, py, 1);
            if (lane == 0) s_ypart[w] = py;
        }
        __syncthreads();   // all h stores of this CTA issued

        // ---- EARLY arrival, then y-partial inside the poll window ----
        // Only the h stores must precede the arrival (fence covers them).
        // The y partial is consumed solely by the post-loop reduction, which
        // is ordered by the extra final barrier round below.
        if (tid == 0) {
            __threadfence();
            atomicAdd(&g_count, 1u);

            float s = 0.f;
            #pragma unroll
            for (int i = 0; i < NWARP; ++i) s += s_ypart[i];
            g_py[(size_t)t * NCTA + cta] = s;   // overlaps others' arrivals

            const unsigned tgt = (unsigned)(t + 1) * NCTA;
            unsigned v;
            do {
                asm volatile("ld.acquire.gpu.global.u32 %0, [%1];"
                             : "=r"(v) : "l"(&g_count) : "memory");
            } while (v < tgt);
        }
        __syncthreads();
    }

    // ---- final barrier round: make every CTA's g_py globally visible ----
    if (tid == 0) {
        __threadfence();
        atomicAdd(&g_count, 1u);
        const unsigned tgt = (unsigned)(SEQ + 1) * NCTA;
        unsigned v;
        do {
            asm volatile("ld.acquire.gpu.global.u32 %0, [%1];"
                         : "=r"(v) : "l"(&g_count) : "memory");
        } while (v < tgt);
    }
    __syncthreads();

    // final h, c
    if (lane < 2) {
        int ug = ubase + lane;
        out[SEQ + ug]     = h_last;
        out[SEQ + H + ug] = c_st;
    }

    // ---- fused y reduction (proven R9/R11) ----
    if (tid < 32) {
        int t = cta * 32 + tid;
        float bo = __ldcg(&b_out[0]);
        const float4* row = (const float4*)(g_py + (size_t)t * NCTA);
        float s = 0.f;
        #pragma unroll
        for (int q = 0; q < NCTA / 4; ++q) {
            float4 v = __ldcg(&row[q]);
            s += ((v.x + v.y) + (v.z + v.w));   // fixed order, q ascending
        }
        out[t] = s + bo;
    }
}

extern "C" void kernel_launch(void* const* d_in, const int* in_sizes, int n_in,
                              void* d_out, int out_size)
{
    (void)in_sizes; (void)n_in; (void)out_size;
    const float* inputs = (const float*)d_in[0];
    const float* w_ih   = (const float*)d_in[1];
    const float* w_hh   = (const float*)d_in[2];
    const float* b_ih   = (const float*)d_in[3];
    const float* b_hh   = (const float*)d_in[4];
    const float* w_out  = (const float*)d_in[5];
    const float* b_out  = (const float*)d_in[6];
    float* out = (float*)d_out;

    cudaFuncSetAttribute(lstm_persistent,
                         cudaFuncAttributeMaxDynamicSharedMemorySize, SMEM_BYTES);

    lstm_init<<<1, 256>>>();
    lstm_persistent<<<NCTA, TPB, SMEM_BYTES>>>(inputs, w_ih, w_hh, b_ih, b_hh,
                                               w_out, b_out, out);
}